// round 1
// baseline (speedup 1.0000x reference)
#include <cuda_runtime.h>
#include <math.h>

#define N_NODES 40000
#define N_EDGES 640000
#define F 128
#define NCLS 16

// ---------------- scratch (no allocations allowed) ----------------
__device__ float g_s[N_NODES * F];     // aggregation accumulator
__device__ float g_deg[N_NODES];       // in-degree (computed once per call)
__device__ float g_rdeg[N_NODES];      // 1 / max(deg, 1)
__device__ float g_h1[N_NODES * F];    // layer-0 output
__device__ float g_h2[N_NODES * F];    // layer-1 output

// ---------------- zero the accumulator (and optionally deg) ----------------
__global__ void zero_s_kernel(int with_deg) {
    int i = blockIdx.x * blockDim.x + threadIdx.x;
    float4* p = reinterpret_cast<float4*>(g_s);
    if (i < N_NODES * (F / 4)) p[i] = make_float4(0.f, 0.f, 0.f, 0.f);
    if (with_deg && i < N_NODES) g_deg[i] = 0.f;
}

// ---------------- edge aggregation: warp per edge ----------------
template <int DO_DEG>
__global__ __launch_bounds__(256) void agg_kernel(
    const float4* __restrict__ hin,   // [N, 32] float4 view of [N,128]
    const float* __restrict__ w,      // [E]
    const int* __restrict__ src,
    const int* __restrict__ dst)
{
    int e = (blockIdx.x * blockDim.x + threadIdx.x) >> 5;
    if (e >= N_EDGES) return;
    int lane = threadIdx.x & 31;

    int s  = __ldg(src + e);
    int d  = __ldg(dst + e);
    float we = __ldg(w + e);

    float4 v = __ldg(hin + (size_t)s * (F / 4) + lane);
    v.x *= we; v.y *= we; v.z *= we; v.w *= we;

    float* p = g_s + (size_t)d * F + lane * 4;
    asm volatile("red.global.add.v4.f32 [%0], {%1,%2,%3,%4};"
                 :: "l"(p), "f"(v.x), "f"(v.y), "f"(v.z), "f"(v.w)
                 : "memory");

    if (DO_DEG && lane == 0) atomicAdd(&g_deg[d], 1.0f);
}

__global__ void rdeg_kernel() {
    int n = blockIdx.x * blockDim.x + threadIdx.x;
    if (n < N_NODES) g_rdeg[n] = 1.0f / fmaxf(g_deg[n], 1.0f);
}

// ---------------- layers 0/1: X[64x256] @ W[128x256]^T + relu + L2-norm ----------------
// X = concat(hin, g_s * rdeg). Block: 128 threads, 64 nodes x 128 outputs,
// thread tile 8 nodes x 8 outputs. K chunked by 32, k-major smem tiles.
__global__ __launch_bounds__(128) void sage_gemm128(
    const float* __restrict__ hin,   // [N,128] layer input
    const float* __restrict__ W,     // [128,256]
    const float* __restrict__ b,     // [128]
    float* __restrict__ out)         // [N,128]
{
    __shared__ float Xs[32][68];     // [k][node], padded
    __shared__ float Ws[32][132];    // [k][j], padded
    __shared__ float norms[64];

    int t = threadIdx.x;
    int n0 = blockIdx.x * 64;
    int jg = t & 15, ng = t >> 4;
    int j0 = jg * 8, nl = ng * 8;

    float acc[8][8];
#pragma unroll
    for (int a = 0; a < 8; ++a)
#pragma unroll
        for (int c = 0; c < 8; ++c) acc[a][c] = 0.f;

    float br[8];
    {
        float4 b0v = __ldg(reinterpret_cast<const float4*>(b) + jg * 2);
        float4 b1v = __ldg(reinterpret_cast<const float4*>(b) + jg * 2 + 1);
        br[0] = b0v.x; br[1] = b0v.y; br[2] = b0v.z; br[3] = b0v.w;
        br[4] = b1v.x; br[5] = b1v.y; br[6] = b1v.z; br[7] = b1v.w;
    }

    const float4* hin4 = reinterpret_cast<const float4*>(hin);
    const float4* s4   = reinterpret_cast<const float4*>(g_s);
    const float4* W4   = reinterpret_cast<const float4*>(W);

    for (int kc = 0; kc < 8; ++kc) {
        // ---- load X chunk (64 nodes x 32 k), transposed into Xs[k][n] ----
#pragma unroll
        for (int i = 0; i < 4; ++i) {
            int q = t + i * 128;          // 512 quads
            int n = q >> 3, kq = q & 7;
            float4 v;
            if (kc < 4) {
                v = __ldg(hin4 + (size_t)(n0 + n) * 32 + (kc * 8 + kq));
            } else {
                v = __ldg(s4 + (size_t)(n0 + n) * 32 + ((kc - 4) * 8 + kq));
                float rd = __ldg(&g_rdeg[n0 + n]);
                v.x *= rd; v.y *= rd; v.z *= rd; v.w *= rd;
            }
            Xs[kq * 4 + 0][n] = v.x;
            Xs[kq * 4 + 1][n] = v.y;
            Xs[kq * 4 + 2][n] = v.z;
            Xs[kq * 4 + 3][n] = v.w;
        }
        // ---- load W chunk (128 j x 32 k), transposed into Ws[k][j] ----
#pragma unroll
        for (int i = 0; i < 8; ++i) {
            int q = t + i * 128;          // 1024 quads
            int j = q >> 3, kq = q & 7;
            float4 v = __ldg(W4 + (size_t)j * 64 + kc * 8 + kq);
            Ws[kq * 4 + 0][j] = v.x;
            Ws[kq * 4 + 1][j] = v.y;
            Ws[kq * 4 + 2][j] = v.z;
            Ws[kq * 4 + 3][j] = v.w;
        }
        __syncthreads();

#pragma unroll 8
        for (int k = 0; k < 32; ++k) {
            float4 xa = *reinterpret_cast<const float4*>(&Xs[k][nl]);
            float4 xb = *reinterpret_cast<const float4*>(&Xs[k][nl + 4]);
            float4 wa = *reinterpret_cast<const float4*>(&Ws[k][j0]);
            float4 wb = *reinterpret_cast<const float4*>(&Ws[k][j0 + 4]);
            float xr[8] = {xa.x, xa.y, xa.z, xa.w, xb.x, xb.y, xb.z, xb.w};
            float wr[8] = {wa.x, wa.y, wa.z, wa.w, wb.x, wb.y, wb.z, wb.w};
#pragma unroll
            for (int nn = 0; nn < 8; ++nn)
#pragma unroll
                for (int jj = 0; jj < 8; ++jj)
                    acc[nn][jj] += xr[nn] * wr[jj];
        }
        __syncthreads();
    }

    // ---- epilogue: relu + row L2 norm ----
    if (t < 64) norms[t] = 0.f;
    __syncthreads();
#pragma unroll
    for (int nn = 0; nn < 8; ++nn) {
        float part = 0.f;
#pragma unroll
        for (int jj = 0; jj < 8; ++jj) {
            float y = fmaxf(acc[nn][jj] + br[jj], 0.f);
            acc[nn][jj] = y;
            part += y * y;
        }
        atomicAdd(&norms[nl + nn], part);
    }
    __syncthreads();
#pragma unroll
    for (int nn = 0; nn < 8; ++nn) {
        float sc = 1.0f / fmaxf(sqrtf(norms[nl + nn]), 1e-12f);
        float4 o0 = make_float4(acc[nn][0] * sc, acc[nn][1] * sc,
                                acc[nn][2] * sc, acc[nn][3] * sc);
        float4 o1 = make_float4(acc[nn][4] * sc, acc[nn][5] * sc,
                                acc[nn][6] * sc, acc[nn][7] * sc);
        float4* orow = reinterpret_cast<float4*>(out + (size_t)(n0 + nl + nn) * F);
        orow[j0 / 4]     = o0;
        orow[j0 / 4 + 1] = o1;
    }
}

// ---------------- layer 2: warp per node, 16 outputs ----------------
__global__ __launch_bounds__(256) void sage_gemm_out(
    const float* __restrict__ hin,   // [N,128]
    const float* __restrict__ W,     // [16,256]
    const float* __restrict__ b,     // [16]
    float* __restrict__ out)         // [N,16]
{
    int n = (blockIdx.x * blockDim.x + threadIdx.x) >> 5;
    if (n >= N_NODES) return;
    int l = threadIdx.x & 31;

    float rd = g_rdeg[n];
    const float* hrow = hin + (size_t)n * F;
    const float* srow = g_s + (size_t)n * F;

    float x[8];
#pragma unroll
    for (int i = 0; i < 8; ++i) {
        int k = l + 32 * i;
        x[i] = (i < 4) ? __ldg(hrow + k) : __ldg(srow + (k - F)) * rd;
    }

    float sj[16];
#pragma unroll
    for (int j = 0; j < 16; ++j) {
        const float* wrow = W + j * 256;
        float a = 0.f;
#pragma unroll
        for (int i = 0; i < 8; ++i) a += x[i] * __ldg(wrow + l + 32 * i);
#pragma unroll
        for (int off = 16; off; off >>= 1)
            a += __shfl_xor_sync(0xffffffffu, a, off);
        sj[j] = a;
    }
    if (l == 0) {
#pragma unroll
        for (int j = 0; j < 16; ++j)
            out[(size_t)n * NCLS + j] = sj[j] + __ldg(b + j);
    }
}

// ---------------- launch ----------------
extern "C" void kernel_launch(void* const* d_in, const int* in_sizes, int n_in,
                              void* d_out, int out_size) {
    const float* h  = (const float*)d_in[0];
    const float* w  = (const float*)d_in[1];
    const int* src  = (const int*)d_in[2];
    const int* dst  = (const int*)d_in[3];
    const float* W0 = (const float*)d_in[4];
    const float* b0 = (const float*)d_in[5];
    const float* W1 = (const float*)d_in[6];
    const float* b1 = (const float*)d_in[7];
    const float* W2 = (const float*)d_in[8];
    const float* b2 = (const float*)d_in[9];
    float* out = (float*)d_out;

    void *ph1 = nullptr, *ph2 = nullptr;
    cudaGetSymbolAddress(&ph1, g_h1);
    cudaGetSymbolAddress(&ph2, g_h2);
    float* h1 = (float*)ph1;
    float* h2 = (float*)ph2;

    const int ZERO_BLOCKS = (N_NODES * (F / 4) + 255) / 256;   // 5000
    const int AGG_BLOCKS  = (N_EDGES * 32) / 256;              // 80000
    const int GEMM_BLOCKS = N_NODES / 64;                      // 625
    const int OUT_BLOCKS  = (N_NODES * 32) / 256;              // 5000
    const int RD_BLOCKS   = (N_NODES + 255) / 256;

    // layer 0
    zero_s_kernel<<<ZERO_BLOCKS, 256>>>(1);
    agg_kernel<1><<<AGG_BLOCKS, 256>>>((const float4*)h, w, src, dst);
    rdeg_kernel<<<RD_BLOCKS, 256>>>();
    sage_gemm128<<<GEMM_BLOCKS, 128>>>(h, W0, b0, h1);

    // layer 1
    zero_s_kernel<<<ZERO_BLOCKS, 256>>>(0);
    agg_kernel<0><<<AGG_BLOCKS, 256>>>((const float4*)h1, w, src, dst);
    sage_gemm128<<<GEMM_BLOCKS, 128>>>(h1, W1, b1, h2);

    // layer 2
    zero_s_kernel<<<ZERO_BLOCKS, 256>>>(0);
    agg_kernel<0><<<AGG_BLOCKS, 256>>>((const float4*)h2, w, src, dst);
    sage_gemm_out<<<OUT_BLOCKS, 256>>>(h2, W2, b2, out);
}

// round 2
// speedup vs baseline: 1.1195x; 1.1195x over previous
#include <cuda_runtime.h>
#include <math.h>
#include <stdint.h>

#define N_NODES 40000
#define N_EDGES 640000
#define F 128
#define NCLS 16

// ---------------- scratch (no allocations allowed) ----------------
__device__ float g_s[N_NODES * F];     // aggregation accumulator
__device__ float g_deg[N_NODES];       // in-degree (computed once per call)
__device__ float g_rdeg[N_NODES];      // 1 / max(deg, 1)
__device__ float g_h1[N_NODES * F];    // layer-0 output
__device__ float g_h2[N_NODES * F];    // layer-1 output

// ---------------- zero the accumulator (and optionally deg) ----------------
__global__ void zero_s_kernel(int with_deg) {
    int i = blockIdx.x * blockDim.x + threadIdx.x;
    float4* p = reinterpret_cast<float4*>(g_s);
    if (i < N_NODES * (F / 4)) p[i] = make_float4(0.f, 0.f, 0.f, 0.f);
    if (with_deg && i < N_NODES) g_deg[i] = 0.f;
}

// ---------------- edge aggregation: warp per edge ----------------
template <int DO_DEG>
__global__ __launch_bounds__(256) void agg_kernel(
    const float4* __restrict__ hin,   // [N, 32] float4 view of [N,128]
    const float* __restrict__ w,      // [E]
    const int* __restrict__ src,
    const int* __restrict__ dst)
{
    int e = (blockIdx.x * blockDim.x + threadIdx.x) >> 5;
    if (e >= N_EDGES) return;
    int lane = threadIdx.x & 31;

    int s  = __ldg(src + e);
    int d  = __ldg(dst + e);
    float we = __ldg(w + e);

    float4 v = __ldg(hin + (size_t)s * (F / 4) + lane);
    v.x *= we; v.y *= we; v.z *= we; v.w *= we;

    float* p = g_s + (size_t)d * F + lane * 4;
    asm volatile("red.global.add.v4.f32 [%0], {%1,%2,%3,%4};"
                 :: "l"(p), "f"(v.x), "f"(v.y), "f"(v.z), "f"(v.w)
                 : "memory");

    if (DO_DEG && lane == 0) atomicAdd(&g_deg[d], 1.0f);
}

__global__ void rdeg_kernel() {
    int n = blockIdx.x * blockDim.x + threadIdx.x;
    if (n < N_NODES) g_rdeg[n] = 1.0f / fmaxf(g_deg[n], 1.0f);
}

// ---------------- 3xTF32 tensor-core GEMM for layers 0/1 ----------------
// out[n][j] = relu( concat(hin, s*rdeg)[n][:] . W[j][:] + b[j] ), then row L2 norm.
// Block: 256 threads (8 warps, 2x4 grid). Tile: 128 nodes x 128 outs, k-chunk 16.
// 3xTF32: x = hi + lo (both tf32); C += ah*bh + ah*bl + al*bh  (fp32-class accuracy).

#define MMA_TF32(c, a, bb) \
    asm volatile("mma.sync.aligned.m16n8k8.row.col.f32.tf32.tf32.f32 " \
                 "{%0,%1,%2,%3}, {%4,%5,%6,%7}, {%8,%9}, {%0,%1,%2,%3};" \
                 : "+f"((c)[0]), "+f"((c)[1]), "+f"((c)[2]), "+f"((c)[3]) \
                 : "r"((a)[0]), "r"((a)[1]), "r"((a)[2]), "r"((a)[3]), \
                   "r"((bb)[0]), "r"((bb)[1]))

__device__ __forceinline__ void tf32_split(float x, float& hi, float& lo) {
    uint32_t hb;
    asm("cvt.rna.tf32.f32 %0, %1;" : "=r"(hb) : "f"(x));
    hi = __uint_as_float(hb);
    float l = x - hi;
    uint32_t lb;
    asm("cvt.rna.tf32.f32 %0, %1;" : "=r"(lb) : "f"(l));
    lo = __uint_as_float(lb);
}

__global__ __launch_bounds__(256) void sage_gemm_tf32(
    const float* __restrict__ hin,   // [N,128] layer input
    const float* __restrict__ W,     // [128,256]
    const float* __restrict__ b,     // [128]
    float* __restrict__ out)         // [N,128]
{
    __shared__ float Ah[16][132], Al[16][132];   // [k][m]
    __shared__ float Bh[16][132], Bl[16][132];   // [k][j]
    __shared__ float norms[128];

    int t = threadIdx.x;
    int n0 = blockIdx.x * 128;
    int warp = t >> 5, lane = t & 31;
    int wr = warp >> 2, wc = warp & 3;
    int row_base = wr * 64;
    int col_base = wc * 32;
    int gid = lane >> 2, tig = lane & 3;

    if (t < 128) norms[t] = 0.f;

    float acc[4][4][4];
#pragma unroll
    for (int mt = 0; mt < 4; ++mt)
#pragma unroll
        for (int nt = 0; nt < 4; ++nt)
#pragma unroll
            for (int c = 0; c < 4; ++c) acc[mt][nt][c] = 0.f;

    const float4* hin4 = reinterpret_cast<const float4*>(hin);
    const float4* s4   = reinterpret_cast<const float4*>(g_s);
    const float4* W4   = reinterpret_cast<const float4*>(W);

    for (int kc = 0; kc < 16; ++kc) {
        int kg = kc * 16;
        __syncthreads();

        // ---- load A chunk: 128 rows x 16 k, hi/lo split, [k][m] transpose ----
#pragma unroll
        for (int i = 0; i < 2; ++i) {
            int q = t + i * 256;               // 512 quads
            int m = q >> 2, f = q & 3;
            int grow = n0 + m;
            float4 v = make_float4(0.f, 0.f, 0.f, 0.f);
            if (grow < N_NODES) {
                if (kg < 128) {
                    v = __ldg(hin4 + (size_t)grow * 32 + (kg >> 2) + f);
                } else {
                    v = __ldg(s4 + (size_t)grow * 32 + ((kg - 128) >> 2) + f);
                    float rd = __ldg(&g_rdeg[grow]);
                    v.x *= rd; v.y *= rd; v.z *= rd; v.w *= rd;
                }
            }
            float xs[4] = {v.x, v.y, v.z, v.w};
#pragma unroll
            for (int c = 0; c < 4; ++c) {
                float hi, lo;
                tf32_split(xs[c], hi, lo);
                Ah[f * 4 + c][m] = hi;
                Al[f * 4 + c][m] = lo;
            }
        }
        // ---- load B chunk: 128 j x 16 k from W[j][k], hi/lo, [k][j] ----
#pragma unroll
        for (int i = 0; i < 2; ++i) {
            int q = t + i * 256;
            int j = q >> 2, f = q & 3;
            float4 v = __ldg(W4 + (size_t)j * 64 + (kg >> 2) + f);
            float xs[4] = {v.x, v.y, v.z, v.w};
#pragma unroll
            for (int c = 0; c < 4; ++c) {
                float hi, lo;
                tf32_split(xs[c], hi, lo);
                Bh[f * 4 + c][j] = hi;
                Bl[f * 4 + c][j] = lo;
            }
        }
        __syncthreads();

        // ---- compute: two k8 sub-steps ----
#pragma unroll
        for (int s = 0; s < 2; ++s) {
            int k0 = s * 8;
            uint32_t bh[4][2], bl[4][2];
#pragma unroll
            for (int nt = 0; nt < 4; ++nt) {
                int j = col_base + nt * 8 + gid;
                bh[nt][0] = __float_as_uint(Bh[k0 + tig][j]);
                bh[nt][1] = __float_as_uint(Bh[k0 + tig + 4][j]);
                bl[nt][0] = __float_as_uint(Bl[k0 + tig][j]);
                bl[nt][1] = __float_as_uint(Bl[k0 + tig + 4][j]);
            }
#pragma unroll
            for (int mt = 0; mt < 4; ++mt) {
                int m = row_base + mt * 16 + gid;
                uint32_t ah[4], al[4];
                ah[0] = __float_as_uint(Ah[k0 + tig][m]);
                ah[1] = __float_as_uint(Ah[k0 + tig][m + 8]);
                ah[2] = __float_as_uint(Ah[k0 + tig + 4][m]);
                ah[3] = __float_as_uint(Ah[k0 + tig + 4][m + 8]);
                al[0] = __float_as_uint(Al[k0 + tig][m]);
                al[1] = __float_as_uint(Al[k0 + tig][m + 8]);
                al[2] = __float_as_uint(Al[k0 + tig + 4][m]);
                al[3] = __float_as_uint(Al[k0 + tig + 4][m + 8]);
#pragma unroll
                for (int nt = 0; nt < 4; ++nt) {
                    MMA_TF32(acc[mt][nt], ah, bh[nt]);
                    MMA_TF32(acc[mt][nt], ah, bl[nt]);
                    MMA_TF32(acc[mt][nt], al, bh[nt]);
                }
            }
        }
    }

    // ---- epilogue: bias + relu + row L2 norm ----
    float2 bias[4];
#pragma unroll
    for (int nt = 0; nt < 4; ++nt)
        bias[nt] = __ldg(reinterpret_cast<const float2*>(b) +
                         (col_base + nt * 8 + 2 * tig) / 2);

#pragma unroll
    for (int mt = 0; mt < 4; ++mt) {
#pragma unroll
        for (int r = 0; r < 2; ++r) {
            float part = 0.f;
#pragma unroll
            for (int nt = 0; nt < 4; ++nt) {
                float y0 = fmaxf(acc[mt][nt][2 * r]     + bias[nt].x, 0.f);
                float y1 = fmaxf(acc[mt][nt][2 * r + 1] + bias[nt].y, 0.f);
                acc[mt][nt][2 * r]     = y0;
                acc[mt][nt][2 * r + 1] = y1;
                part += y0 * y0 + y1 * y1;
            }
            part += __shfl_xor_sync(0xffffffffu, part, 1);
            part += __shfl_xor_sync(0xffffffffu, part, 2);
            if (tig == 0)
                atomicAdd(&norms[row_base + mt * 16 + gid + r * 8], part);
        }
    }
    __syncthreads();

#pragma unroll
    for (int mt = 0; mt < 4; ++mt) {
#pragma unroll
        for (int r = 0; r < 2; ++r) {
            int lrow = row_base + mt * 16 + gid + r * 8;
            int grow = n0 + lrow;
            if (grow < N_NODES) {
                float sc = 1.0f / fmaxf(sqrtf(norms[lrow]), 1e-12f);
#pragma unroll
                for (int nt = 0; nt < 4; ++nt) {
                    float2 o = make_float2(acc[mt][nt][2 * r] * sc,
                                           acc[mt][nt][2 * r + 1] * sc);
                    *reinterpret_cast<float2*>(out + (size_t)grow * F +
                                               col_base + nt * 8 + 2 * tig) = o;
                }
            }
        }
    }
}

// ---------------- layer 2: warp per node, 16 outputs ----------------
__global__ __launch_bounds__(256) void sage_gemm_out(
    const float* __restrict__ hin,   // [N,128]
    const float* __restrict__ W,     // [16,256]
    const float* __restrict__ b,     // [16]
    float* __restrict__ out)         // [N,16]
{
    int n = (blockIdx.x * blockDim.x + threadIdx.x) >> 5;
    if (n >= N_NODES) return;
    int l = threadIdx.x & 31;

    float rd = g_rdeg[n];
    const float* hrow = hin + (size_t)n * F;
    const float* srow = g_s + (size_t)n * F;

    float x[8];
#pragma unroll
    for (int i = 0; i < 8; ++i) {
        int k = l + 32 * i;
        x[i] = (i < 4) ? __ldg(hrow + k) : __ldg(srow + (k - F)) * rd;
    }

    float sj[16];
#pragma unroll
    for (int j = 0; j < 16; ++j) {
        const float* wrow = W + j * 256;
        float a = 0.f;
#pragma unroll
        for (int i = 0; i < 8; ++i) a += x[i] * __ldg(wrow + l + 32 * i);
#pragma unroll
        for (int off = 16; off; off >>= 1)
            a += __shfl_xor_sync(0xffffffffu, a, off);
        sj[j] = a;
    }
    if (l == 0) {
#pragma unroll
        for (int j = 0; j < 16; ++j)
            out[(size_t)n * NCLS + j] = sj[j] + __ldg(b + j);
    }
}

// ---------------- launch ----------------
extern "C" void kernel_launch(void* const* d_in, const int* in_sizes, int n_in,
                              void* d_out, int out_size) {
    const float* h  = (const float*)d_in[0];
    const float* w  = (const float*)d_in[1];
    const int* src  = (const int*)d_in[2];
    const int* dst  = (const int*)d_in[3];
    const float* W0 = (const float*)d_in[4];
    const float* b0 = (const float*)d_in[5];
    const float* W1 = (const float*)d_in[6];
    const float* b1 = (const float*)d_in[7];
    const float* W2 = (const float*)d_in[8];
    const float* b2 = (const float*)d_in[9];
    float* out = (float*)d_out;

    void *ph1 = nullptr, *ph2 = nullptr;
    cudaGetSymbolAddress(&ph1, g_h1);
    cudaGetSymbolAddress(&ph2, g_h2);
    float* h1 = (float*)ph1;
    float* h2 = (float*)ph2;

    const int ZERO_BLOCKS = (N_NODES * (F / 4) + 255) / 256;   // 5000
    const int AGG_BLOCKS  = (N_EDGES * 32) / 256;              // 80000
    const int GEMM_BLOCKS = (N_NODES + 127) / 128;             // 313
    const int OUT_BLOCKS  = (N_NODES * 32) / 256;              // 5000
    const int RD_BLOCKS   = (N_NODES + 255) / 256;

    // layer 0
    zero_s_kernel<<<ZERO_BLOCKS, 256>>>(1);
    agg_kernel<1><<<AGG_BLOCKS, 256>>>((const float4*)h, w, src, dst);
    rdeg_kernel<<<RD_BLOCKS, 256>>>();
    sage_gemm_tf32<<<GEMM_BLOCKS, 256>>>(h, W0, b0, h1);

    // layer 1
    zero_s_kernel<<<ZERO_BLOCKS, 256>>>(0);
    agg_kernel<0><<<AGG_BLOCKS, 256>>>((const float4*)h1, w, src, dst);
    sage_gemm_tf32<<<GEMM_BLOCKS, 256>>>(h1, W1, b1, h2);

    // layer 2
    zero_s_kernel<<<ZERO_BLOCKS, 256>>>(0);
    agg_kernel<0><<<AGG_BLOCKS, 256>>>((const float4*)h2, w, src, dst);
    sage_gemm_out<<<OUT_BLOCKS, 256>>>(h2, W2, b2, out);
}

// round 3
// speedup vs baseline: 1.3350x; 1.1924x over previous
#include <cuda_runtime.h>
#include <math.h>
#include <stdint.h>

#define N_NODES 40000
#define N_EDGES 640000
#define F 128
#define NCLS 16

// ---------------- scratch (no allocations allowed) ----------------
__device__ float g_s[N_NODES * F];       // aggregation result (already meaned)
__device__ float g_h1[N_NODES * F];      // layer-0 output
__device__ float g_h2[N_NODES * F];      // layer-1 output
__device__ int   g_cnt[N_NODES];         // histogram / scatter cursor
__device__ int   g_off[N_NODES + 1];     // CSR offsets
__device__ int   g_ssrc[N_EDGES];        // CSR-sorted src
__device__ float g_sw[N_EDGES];          // CSR-sorted edge weight
__device__ float g_Whi[256 * 128];       // pre-split weight hi, k-major [k][j]
__device__ float g_Wlo[256 * 128];       // pre-split weight lo, k-major [k][j]

// ---------------- tf32 helpers ----------------
#define MMA_TF32(c, a, bb) \
    asm volatile("mma.sync.aligned.m16n8k8.row.col.f32.tf32.tf32.f32 " \
                 "{%0,%1,%2,%3}, {%4,%5,%6,%7}, {%8,%9}, {%0,%1,%2,%3};" \
                 : "+f"((c)[0]), "+f"((c)[1]), "+f"((c)[2]), "+f"((c)[3]) \
                 : "r"((a)[0]), "r"((a)[1]), "r"((a)[2]), "r"((a)[3]), \
                   "r"((bb)[0]), "r"((bb)[1]))

__device__ __forceinline__ void tf32_split(float x, float& hi, float& lo) {
    uint32_t hb;
    asm("cvt.rna.tf32.f32 %0, %1;" : "=r"(hb) : "f"(x));
    hi = __uint_as_float(hb);
    float l = x - hi;
    uint32_t lb;
    asm("cvt.rna.tf32.f32 %0, %1;" : "=r"(lb) : "f"(l));
    lo = __uint_as_float(lb);
}

__device__ __forceinline__ void cp_async16(void* smem_dst, const void* gsrc) {
    uint32_t d = (uint32_t)__cvta_generic_to_shared(smem_dst);
    asm volatile("cp.async.ca.shared.global [%0], [%1], 16;" :: "r"(d), "l"(gsrc));
}

// ---------------- CSR build ----------------
__global__ void zero_cnt_kernel() {
    int i = blockIdx.x * blockDim.x + threadIdx.x;
    if (i < N_NODES) g_cnt[i] = 0;
}

__global__ void hist_kernel(const int* __restrict__ dst) {
    int e = blockIdx.x * blockDim.x + threadIdx.x;
    if (e < N_EDGES) atomicAdd(&g_cnt[dst[e]], 1);
}

__global__ __launch_bounds__(1024) void scan_kernel() {
    __shared__ int part[1024];
    int t = threadIdx.x;
    const int C = (N_NODES + 1023) / 1024;            // 40
    int beg = t * C, end = min(beg + C, N_NODES);
    int s = 0;
    for (int i = beg; i < end; ++i) s += g_cnt[i];
    part[t] = s;
    __syncthreads();
    for (int off = 1; off < 1024; off <<= 1) {
        int v = (t >= off) ? part[t - off] : 0;
        __syncthreads();
        part[t] += v;
        __syncthreads();
    }
    int run = part[t] - s;                            // exclusive
    for (int i = beg; i < end; ++i) {
        g_off[i] = run;
        run += g_cnt[i];
        g_cnt[i] = 0;                                 // reset for scatter cursor
    }
    if (t == 1023) g_off[N_NODES] = run;
}

__global__ void scatter_kernel(const int* __restrict__ src,
                               const int* __restrict__ dst,
                               const float* __restrict__ w) {
    int e = blockIdx.x * blockDim.x + threadIdx.x;
    if (e >= N_EDGES) return;
    int d = dst[e];
    int p = g_off[d] + atomicAdd(&g_cnt[d], 1);
    g_ssrc[p] = src[e];
    g_sw[p]   = w[e];
}

// ---------------- aggregation: warp per node, register accumulate ----------------
__global__ __launch_bounds__(256) void agg_csr_kernel(const float4* __restrict__ hin) {
    int n = (blockIdx.x * blockDim.x + threadIdx.x) >> 5;
    if (n >= N_NODES) return;
    int lane = threadIdx.x & 31;
    int beg = g_off[n], end = g_off[n + 1];

    float4 a0 = make_float4(0.f, 0.f, 0.f, 0.f);
    float4 a1 = make_float4(0.f, 0.f, 0.f, 0.f);
    int e = beg;
    for (; e + 2 <= end; e += 2) {
        int s0 = __ldg(g_ssrc + e), s1 = __ldg(g_ssrc + e + 1);
        float w0 = __ldg(g_sw + e), w1 = __ldg(g_sw + e + 1);
        float4 v0 = __ldg(hin + (size_t)s0 * 32 + lane);
        float4 v1 = __ldg(hin + (size_t)s1 * 32 + lane);
        a0.x += w0 * v0.x; a0.y += w0 * v0.y; a0.z += w0 * v0.z; a0.w += w0 * v0.w;
        a1.x += w1 * v1.x; a1.y += w1 * v1.y; a1.z += w1 * v1.z; a1.w += w1 * v1.w;
    }
    if (e < end) {
        int s0 = __ldg(g_ssrc + e);
        float w0 = __ldg(g_sw + e);
        float4 v0 = __ldg(hin + (size_t)s0 * 32 + lane);
        a0.x += w0 * v0.x; a0.y += w0 * v0.y; a0.z += w0 * v0.z; a0.w += w0 * v0.w;
    }
    float inv = (end > beg) ? 1.0f / (float)(end - beg) : 0.0f;
    float4 r = make_float4((a0.x + a1.x) * inv, (a0.y + a1.y) * inv,
                           (a0.z + a1.z) * inv, (a0.w + a1.w) * inv);
    reinterpret_cast<float4*>(g_s)[(size_t)n * 32 + lane] = r;
}

// ---------------- weight pre-split: W[j][k] -> g_Whi/g_Wlo [k][j] ----------------
__global__ void wsplit_kernel(const float* __restrict__ W) {
    int i = blockIdx.x * blockDim.x + threadIdx.x;
    if (i >= 128 * 256) return;
    int j = i >> 8, k = i & 255;
    float hi, lo;
    tf32_split(W[i], hi, lo);
    g_Whi[k * 128 + j] = hi;
    g_Wlo[k * 128 + j] = lo;
}

// ---------------- 3xTF32 GEMM, double-buffered, cp.async B ----------------
// Tile 128 nodes x 128 outs, k-chunk 16, 8 warps (2x4), warp tile 64x32.
// A smem row-major [m][k] stride 20 (fragment LDS conflict-free: banks 20m+k).
// B smem k-major  [k][j] stride 136 (fragment LDS conflict-free: banks 8k+j).
#define ASZ (128 * 20)
#define BSZ (16 * 136)
#define GEMM_SMEM_BYTES ((4 * ASZ + 4 * BSZ + 128) * 4)

__global__ __launch_bounds__(256, 2) void sage_gemm_tf32(
    const float* __restrict__ hin,   // [N,128] layer input
    const float* __restrict__ b,     // [128]
    float* __restrict__ out)         // [N,128]
{
    extern __shared__ float smem[];
    float* AhB = smem;                    // [2][ASZ]
    float* AlB = AhB + 2 * ASZ;
    float* BhB = AlB + 2 * ASZ;           // [2][BSZ]
    float* BlB = BhB + 2 * BSZ;
    float* norms = BlB + 2 * BSZ;         // [128]

    int t = threadIdx.x;
    int n0 = blockIdx.x * 128;
    int warp = t >> 5, lane = t & 31;
    int wr = warp >> 2, wc = warp & 3;
    int row_base = wr * 64;
    int col_base = wc * 32;
    int gid = lane >> 2, tig = lane & 3;

    if (t < 128) norms[t] = 0.f;

    float acc[4][4][4];
#pragma unroll
    for (int mt = 0; mt < 4; ++mt)
#pragma unroll
        for (int nt = 0; nt < 4; ++nt)
#pragma unroll
            for (int c = 0; c < 4; ++c) acc[mt][nt][c] = 0.f;

    const float4* hin4 = reinterpret_cast<const float4*>(hin);
    const float4* s4   = reinterpret_cast<const float4*>(g_s);

    // per-thread A quad coords (2 quads)
    int m_[2], f_[2];
#pragma unroll
    for (int i = 0; i < 2; ++i) { int q = t + i * 256; m_[i] = q >> 2; f_[i] = q & 3; }
    // per-thread B quad coords (2 quads)
    int bk_[2], bj_[2];
#pragma unroll
    for (int i = 0; i < 2; ++i) { int q = t + i * 256; bk_[i] = q >> 5; bj_[i] = q & 31; }

    // ---- helpers as lambdas ----
    auto load_a = [&](int kg, float4 v[2]) {
#pragma unroll
        for (int i = 0; i < 2; ++i) {
            int grow = n0 + m_[i];
            float4 x = make_float4(0.f, 0.f, 0.f, 0.f);
            if (grow < N_NODES) {
                x = (kg < 128)
                    ? __ldg(hin4 + (size_t)grow * 32 + (kg >> 2) + f_[i])
                    : __ldg(s4   + (size_t)grow * 32 + ((kg - 128) >> 2) + f_[i]);
            }
            v[i] = x;
        }
    };
    auto store_a = [&](int buf, const float4 v[2]) {
        float* Ah = AhB + buf * ASZ;
        float* Al = AlB + buf * ASZ;
#pragma unroll
        for (int i = 0; i < 2; ++i) {
            float xs[4] = {v[i].x, v[i].y, v[i].z, v[i].w};
            float h4[4], l4[4];
#pragma unroll
            for (int c = 0; c < 4; ++c) tf32_split(xs[c], h4[c], l4[c]);
            int base = m_[i] * 20 + f_[i] * 4;
            *reinterpret_cast<float4*>(Ah + base) = make_float4(h4[0], h4[1], h4[2], h4[3]);
            *reinterpret_cast<float4*>(Al + base) = make_float4(l4[0], l4[1], l4[2], l4[3]);
        }
    };
    auto issue_b = [&](int kg, int buf) {
        float* Bh = BhB + buf * BSZ;
        float* Bl = BlB + buf * BSZ;
#pragma unroll
        for (int i = 0; i < 2; ++i) {
            int off = bk_[i] * 136 + bj_[i] * 4;
            cp_async16(Bh + off, g_Whi + (size_t)(kg + bk_[i]) * 128 + bj_[i] * 4);
            cp_async16(Bl + off, g_Wlo + (size_t)(kg + bk_[i]) * 128 + bj_[i] * 4);
        }
        asm volatile("cp.async.commit_group;");
    };

    // ---- prologue: chunk 0 ----
    float4 av[2];
    issue_b(0, 0);
    load_a(0, av);
    store_a(0, av);
    asm volatile("cp.async.wait_group 0;");
    __syncthreads();

    for (int kc = 0; kc < 16; ++kc) {
        int cur = kc & 1;
        float4 nav[2];
        if (kc < 15) {
            issue_b((kc + 1) * 16, cur ^ 1);
            load_a((kc + 1) * 16, nav);
        }

        // ---- compute chunk kc ----
        {
            const float* Ah = AhB + cur * ASZ;
            const float* Al = AlB + cur * ASZ;
            const float* Bh = BhB + cur * BSZ;
            const float* Bl = BlB + cur * BSZ;
#pragma unroll
            for (int s = 0; s < 2; ++s) {
                int k0 = s * 8;
                uint32_t bh[4][2], bl[4][2];
#pragma unroll
                for (int nt = 0; nt < 4; ++nt) {
                    int j = col_base + nt * 8 + gid;
                    bh[nt][0] = __float_as_uint(Bh[(k0 + tig) * 136 + j]);
                    bh[nt][1] = __float_as_uint(Bh[(k0 + tig + 4) * 136 + j]);
                    bl[nt][0] = __float_as_uint(Bl[(k0 + tig) * 136 + j]);
                    bl[nt][1] = __float_as_uint(Bl[(k0 + tig + 4) * 136 + j]);
                }
#pragma unroll
                for (int mt = 0; mt < 4; ++mt) {
                    int m = row_base + mt * 16 + gid;
                    uint32_t ah[4], al[4];
                    ah[0] = __float_as_uint(Ah[m * 20 + k0 + tig]);
                    ah[1] = __float_as_uint(Ah[(m + 8) * 20 + k0 + tig]);
                    ah[2] = __float_as_uint(Ah[m * 20 + k0 + tig + 4]);
                    ah[3] = __float_as_uint(Ah[(m + 8) * 20 + k0 + tig + 4]);
                    al[0] = __float_as_uint(Al[m * 20 + k0 + tig]);
                    al[1] = __float_as_uint(Al[(m + 8) * 20 + k0 + tig]);
                    al[2] = __float_as_uint(Al[m * 20 + k0 + tig + 4]);
                    al[3] = __float_as_uint(Al[(m + 8) * 20 + k0 + tig + 4]);
#pragma unroll
                    for (int nt = 0; nt < 4; ++nt) {
                        MMA_TF32(acc[mt][nt], ah, bh[nt]);
                        MMA_TF32(acc[mt][nt], ah, bl[nt]);
                        MMA_TF32(acc[mt][nt], al, bh[nt]);
                    }
                }
            }
        }

        if (kc < 15) store_a(cur ^ 1, nav);
        asm volatile("cp.async.wait_group 0;");
        __syncthreads();
    }

    // ---- epilogue: bias + relu + row L2 norm ----
    float2 bias[4];
#pragma unroll
    for (int nt = 0; nt < 4; ++nt)
        bias[nt] = __ldg(reinterpret_cast<const float2*>(b) +
                         (col_base + nt * 8 + 2 * tig) / 2);

#pragma unroll
    for (int mt = 0; mt < 4; ++mt) {
#pragma unroll
        for (int r = 0; r < 2; ++r) {
            float part = 0.f;
#pragma unroll
            for (int nt = 0; nt < 4; ++nt) {
                float y0 = fmaxf(acc[mt][nt][2 * r]     + bias[nt].x, 0.f);
                float y1 = fmaxf(acc[mt][nt][2 * r + 1] + bias[nt].y, 0.f);
                acc[mt][nt][2 * r]     = y0;
                acc[mt][nt][2 * r + 1] = y1;
                part += y0 * y0 + y1 * y1;
            }
            part += __shfl_xor_sync(0xffffffffu, part, 1);
            part += __shfl_xor_sync(0xffffffffu, part, 2);
            if (tig == 0)
                atomicAdd(&norms[row_base + mt * 16 + gid + r * 8], part);
        }
    }
    __syncthreads();

#pragma unroll
    for (int mt = 0; mt < 4; ++mt) {
#pragma unroll
        for (int r = 0; r < 2; ++r) {
            int lrow = row_base + mt * 16 + gid + r * 8;
            int grow = n0 + lrow;
            if (grow < N_NODES) {
                float sc = 1.0f / fmaxf(sqrtf(norms[lrow]), 1e-12f);
#pragma unroll
                for (int nt = 0; nt < 4; ++nt) {
                    float2 o = make_float2(acc[mt][nt][2 * r] * sc,
                                           acc[mt][nt][2 * r + 1] * sc);
                    *reinterpret_cast<float2*>(out + (size_t)grow * F +
                                               col_base + nt * 8 + 2 * tig) = o;
                }
            }
        }
    }
}

// ---------------- layer 2: warp per node, 16 outputs ----------------
__global__ __launch_bounds__(256) void sage_gemm_out(
    const float* __restrict__ hin,   // [N,128]
    const float* __restrict__ W,     // [16,256]
    const float* __restrict__ b,     // [16]
    float* __restrict__ out)         // [N,16]
{
    int n = (blockIdx.x * blockDim.x + threadIdx.x) >> 5;
    if (n >= N_NODES) return;
    int l = threadIdx.x & 31;

    const float* hrow = hin + (size_t)n * F;
    const float* srow = g_s + (size_t)n * F;

    float x[8];
#pragma unroll
    for (int i = 0; i < 8; ++i) {
        int k = l + 32 * i;
        x[i] = (i < 4) ? __ldg(hrow + k) : __ldg(srow + (k - F));
    }

    float sj[16];
#pragma unroll
    for (int j = 0; j < 16; ++j) {
        const float* wrow = W + j * 256;
        float a = 0.f;
#pragma unroll
        for (int i = 0; i < 8; ++i) a += x[i] * __ldg(wrow + l + 32 * i);
#pragma unroll
        for (int off = 16; off; off >>= 1)
            a += __shfl_xor_sync(0xffffffffu, a, off);
        sj[j] = a;
    }
    if (l == 0) {
#pragma unroll
        for (int j = 0; j < 16; ++j)
            out[(size_t)n * NCLS + j] = sj[j] + __ldg(b + j);
    }
}

// ---------------- launch ----------------
extern "C" void kernel_launch(void* const* d_in, const int* in_sizes, int n_in,
                              void* d_out, int out_size) {
    const float* h  = (const float*)d_in[0];
    const float* w  = (const float*)d_in[1];
    const int* src  = (const int*)d_in[2];
    const int* dst  = (const int*)d_in[3];
    const float* W0 = (const float*)d_in[4];
    const float* b0 = (const float*)d_in[5];
    const float* W1 = (const float*)d_in[6];
    const float* b1 = (const float*)d_in[7];
    const float* W2 = (const float*)d_in[8];
    const float* b2 = (const float*)d_in[9];
    float* out = (float*)d_out;

    void *ph1 = nullptr, *ph2 = nullptr;
    cudaGetSymbolAddress(&ph1, g_h1);
    cudaGetSymbolAddress(&ph2, g_h2);
    float* h1 = (float*)ph1;
    float* h2 = (float*)ph2;

    cudaFuncSetAttribute(sage_gemm_tf32,
                         cudaFuncAttributeMaxDynamicSharedMemorySize,
                         GEMM_SMEM_BYTES);

    const int NODE_BLOCKS = (N_NODES + 255) / 256;             // 157
    const int EDGE_BLOCKS = (N_EDGES + 255) / 256;             // 2500
    const int AGG_BLOCKS  = (N_NODES * 32 + 255) / 256;        // 5000
    const int GEMM_BLOCKS = (N_NODES + 127) / 128;             // 313
    const int OUT_BLOCKS  = (N_NODES * 32 + 255) / 256;        // 5000
    const int WSP_BLOCKS  = (128 * 256 + 255) / 256;           // 128

    // CSR build (once per call, reused by all 3 layers)
    zero_cnt_kernel<<<NODE_BLOCKS, 256>>>();
    hist_kernel<<<EDGE_BLOCKS, 256>>>(dst);
    scan_kernel<<<1, 1024>>>();
    scatter_kernel<<<EDGE_BLOCKS, 256>>>(src, dst, w);

    // layer 0
    wsplit_kernel<<<WSP_BLOCKS, 256>>>(W0);
    agg_csr_kernel<<<AGG_BLOCKS, 256>>>((const float4*)h);
    sage_gemm_tf32<<<GEMM_BLOCKS, 256, GEMM_SMEM_BYTES>>>(h, b0, h1);

    // layer 1
    wsplit_kernel<<<WSP_BLOCKS, 256>>>(W1);
    agg_csr_kernel<<<AGG_BLOCKS, 256>>>((const float4*)h1);
    sage_gemm_tf32<<<GEMM_BLOCKS, 256, GEMM_SMEM_BYTES>>>(h1, b1, h2);

    // layer 2
    agg_csr_kernel<<<AGG_BLOCKS, 256>>>((const float4*)h2);
    sage_gemm_out<<<OUT_BLOCKS, 256>>>(h2, W2, b2, out);
}

// round 4
// speedup vs baseline: 1.3697x; 1.0260x over previous
#include <cuda_runtime.h>
#include <math.h>
#include <stdint.h>

#define N_NODES 40000
#define N_EDGES 640000
#define F 128
#define NCLS 16

// ---------------- scratch (no allocations allowed) ----------------
__device__ float g_s[N_NODES * F];       // aggregation result / layer-2 pn
__device__ float g_h1[N_NODES * F];      // layer-0 output / layer-2 pself
__device__ float g_h2[N_NODES * F];      // layer-1 output
__device__ int   g_cnt[N_NODES];         // histogram / scatter cursor
__device__ int   g_off[N_NODES + 1];     // CSR offsets
__device__ int2  g_edge[N_EDGES];        // CSR-sorted (src, w_bits)
__device__ float g_Whi[2 * 256 * 128];   // pre-split weight hi, k-major [layer][k][j]
__device__ float g_Wlo[2 * 256 * 128];   // pre-split weight lo, k-major [layer][k][j]

// ---------------- tf32 helpers ----------------
#define MMA_TF32(c, a, bb) \
    asm volatile("mma.sync.aligned.m16n8k8.row.col.f32.tf32.tf32.f32 " \
                 "{%0,%1,%2,%3}, {%4,%5,%6,%7}, {%8,%9}, {%0,%1,%2,%3};" \
                 : "+f"((c)[0]), "+f"((c)[1]), "+f"((c)[2]), "+f"((c)[3]) \
                 : "r"((a)[0]), "r"((a)[1]), "r"((a)[2]), "r"((a)[3]), \
                   "r"((bb)[0]), "r"((bb)[1]))

__device__ __forceinline__ void tf32_split(float x, float& hi, float& lo) {
    uint32_t hb;
    asm("cvt.rna.tf32.f32 %0, %1;" : "=r"(hb) : "f"(x));
    hi = __uint_as_float(hb);
    float l = x - hi;
    uint32_t lb;
    asm("cvt.rna.tf32.f32 %0, %1;" : "=r"(lb) : "f"(l));
    lo = __uint_as_float(lb);
}

__device__ __forceinline__ void cp_async16(void* smem_dst, const void* gsrc) {
    uint32_t d = (uint32_t)__cvta_generic_to_shared(smem_dst);
    asm volatile("cp.async.ca.shared.global [%0], [%1], 16;" :: "r"(d), "l"(gsrc));
}

// ---------------- weight pre-split: both layers in one launch ----------------
__global__ void wsplit_all_kernel(const float* __restrict__ W0,
                                  const float* __restrict__ W1) {
    int i = blockIdx.x * blockDim.x + threadIdx.x;
    if (i >= 2 * 128 * 256) return;
    int layer = i >> 15;
    int r = i & 32767;
    int j = r >> 8, k = r & 255;
    const float* W = layer ? W1 : W0;
    float hi, lo;
    tf32_split(W[r], hi, lo);
    g_Whi[layer * 32768 + k * 128 + j] = hi;
    g_Wlo[layer * 32768 + k * 128 + j] = lo;
}

// ---------------- CSR build ----------------
__global__ void zero_cnt_kernel() {
    int i = blockIdx.x * blockDim.x + threadIdx.x;
    if (i < N_NODES) g_cnt[i] = 0;
}

__global__ void hist_kernel(const int* __restrict__ dst) {
    int e = blockIdx.x * blockDim.x + threadIdx.x;
    if (e < N_EDGES) atomicAdd(&g_cnt[dst[e]], 1);
}

__global__ __launch_bounds__(1024) void scan_kernel() {
    __shared__ int part[1024];
    int t = threadIdx.x;
    const int C = (N_NODES + 1023) / 1024;            // 40
    int beg = t * C, end = min(beg + C, N_NODES);
    int s = 0;
    for (int i = beg; i < end; ++i) s += g_cnt[i];
    part[t] = s;
    __syncthreads();
    for (int off = 1; off < 1024; off <<= 1) {
        int v = (t >= off) ? part[t - off] : 0;
        __syncthreads();
        part[t] += v;
        __syncthreads();
    }
    int run = part[t] - s;                            // exclusive
    for (int i = beg; i < end; ++i) {
        g_off[i] = run;
        run += g_cnt[i];
        g_cnt[i] = 0;                                 // reset for scatter cursor
    }
    if (t == 1023) g_off[N_NODES] = run;
}

__global__ void scatter_kernel(const int* __restrict__ src,
                               const int* __restrict__ dst,
                               const float* __restrict__ w) {
    int e = blockIdx.x * blockDim.x + threadIdx.x;
    if (e >= N_EDGES) return;
    int d = dst[e];
    int p = g_off[d] + atomicAdd(&g_cnt[d], 1);
    g_edge[p] = make_int2(src[e], __float_as_int(w[e]));
}

// ---------------- aggregation (d=128): warp per node, register accumulate ----------------
__global__ __launch_bounds__(256) void agg_csr_kernel(const float4* __restrict__ hin) {
    int n = (blockIdx.x * blockDim.x + threadIdx.x) >> 5;
    if (n >= N_NODES) return;
    int lane = threadIdx.x & 31;
    int beg = g_off[n], end = g_off[n + 1];

    float4 a0 = make_float4(0.f, 0.f, 0.f, 0.f);
    float4 a1 = make_float4(0.f, 0.f, 0.f, 0.f);
    int e = beg;
    for (; e + 2 <= end; e += 2) {
        int2 e0 = __ldg(g_edge + e);
        int2 e1 = __ldg(g_edge + e + 1);
        float w0 = __int_as_float(e0.y), w1 = __int_as_float(e1.y);
        float4 v0 = __ldg(hin + (size_t)e0.x * 32 + lane);
        float4 v1 = __ldg(hin + (size_t)e1.x * 32 + lane);
        a0.x += w0 * v0.x; a0.y += w0 * v0.y; a0.z += w0 * v0.z; a0.w += w0 * v0.w;
        a1.x += w1 * v1.x; a1.y += w1 * v1.y; a1.z += w1 * v1.z; a1.w += w1 * v1.w;
    }
    if (e < end) {
        int2 e0 = __ldg(g_edge + e);
        float w0 = __int_as_float(e0.y);
        float4 v0 = __ldg(hin + (size_t)e0.x * 32 + lane);
        a0.x += w0 * v0.x; a0.y += w0 * v0.y; a0.z += w0 * v0.z; a0.w += w0 * v0.w;
    }
    float inv = (end > beg) ? 1.0f / (float)(end - beg) : 0.0f;
    float4 r = make_float4((a0.x + a1.x) * inv, (a0.y + a1.y) * inv,
                           (a0.z + a1.z) * inv, (a0.w + a1.w) * inv);
    reinterpret_cast<float4*>(g_s)[(size_t)n * 32 + lane] = r;
}

// ---------------- 3xTF32 GEMM, double-buffered, cp.async B ----------------
#define ASZ (128 * 20)
#define BSZ (16 * 136)
#define GEMM_SMEM_BYTES ((4 * ASZ + 4 * BSZ + 128) * 4)

__global__ __launch_bounds__(256, 2) void sage_gemm_tf32(
    const float* __restrict__ hin,   // [N,128] layer input
    const float* __restrict__ b,     // [128]
    float* __restrict__ out,         // [N,128]
    int layer)
{
    extern __shared__ float smem[];
    float* AhB = smem;                    // [2][ASZ]
    float* AlB = AhB + 2 * ASZ;
    float* BhB = AlB + 2 * ASZ;           // [2][BSZ]
    float* BlB = BhB + 2 * BSZ;
    float* norms = BlB + 2 * BSZ;         // [128]

    const float* Whi = g_Whi + layer * 32768;
    const float* Wlo = g_Wlo + layer * 32768;

    int t = threadIdx.x;
    int n0 = blockIdx.x * 128;
    int warp = t >> 5, lane = t & 31;
    int wr = warp >> 2, wc = warp & 3;
    int row_base = wr * 64;
    int col_base = wc * 32;
    int gid = lane >> 2, tig = lane & 3;

    if (t < 128) norms[t] = 0.f;

    float acc[4][4][4];
#pragma unroll
    for (int mt = 0; mt < 4; ++mt)
#pragma unroll
        for (int nt = 0; nt < 4; ++nt)
#pragma unroll
            for (int c = 0; c < 4; ++c) acc[mt][nt][c] = 0.f;

    const float4* hin4 = reinterpret_cast<const float4*>(hin);
    const float4* s4   = reinterpret_cast<const float4*>(g_s);

    int m_[2], f_[2];
#pragma unroll
    for (int i = 0; i < 2; ++i) { int q = t + i * 256; m_[i] = q >> 2; f_[i] = q & 3; }
    int bk_[2], bj_[2];
#pragma unroll
    for (int i = 0; i < 2; ++i) { int q = t + i * 256; bk_[i] = q >> 5; bj_[i] = q & 31; }

    auto load_a = [&](int kg, float4 v[2]) {
#pragma unroll
        for (int i = 0; i < 2; ++i) {
            int grow = n0 + m_[i];
            float4 x = make_float4(0.f, 0.f, 0.f, 0.f);
            if (grow < N_NODES) {
                x = (kg < 128)
                    ? __ldg(hin4 + (size_t)grow * 32 + (kg >> 2) + f_[i])
                    : __ldg(s4   + (size_t)grow * 32 + ((kg - 128) >> 2) + f_[i]);
            }
            v[i] = x;
        }
    };
    auto store_a = [&](int buf, const float4 v[2]) {
        float* Ah = AhB + buf * ASZ;
        float* Al = AlB + buf * ASZ;
#pragma unroll
        for (int i = 0; i < 2; ++i) {
            float xs[4] = {v[i].x, v[i].y, v[i].z, v[i].w};
            float h4[4], l4[4];
#pragma unroll
            for (int c = 0; c < 4; ++c) tf32_split(xs[c], h4[c], l4[c]);
            int base = m_[i] * 20 + f_[i] * 4;
            *reinterpret_cast<float4*>(Ah + base) = make_float4(h4[0], h4[1], h4[2], h4[3]);
            *reinterpret_cast<float4*>(Al + base) = make_float4(l4[0], l4[1], l4[2], l4[3]);
        }
    };
    auto issue_b = [&](int kg, int buf) {
        float* Bh = BhB + buf * BSZ;
        float* Bl = BlB + buf * BSZ;
#pragma unroll
        for (int i = 0; i < 2; ++i) {
            int off = bk_[i] * 136 + bj_[i] * 4;
            cp_async16(Bh + off, Whi + (size_t)(kg + bk_[i]) * 128 + bj_[i] * 4);
            cp_async16(Bl + off, Wlo + (size_t)(kg + bk_[i]) * 128 + bj_[i] * 4);
        }
        asm volatile("cp.async.commit_group;");
    };

    float4 av[2];
    issue_b(0, 0);
    load_a(0, av);
    store_a(0, av);
    asm volatile("cp.async.wait_group 0;");
    __syncthreads();

    for (int kc = 0; kc < 16; ++kc) {
        int cur = kc & 1;
        float4 nav[2];
        if (kc < 15) {
            issue_b((kc + 1) * 16, cur ^ 1);
            load_a((kc + 1) * 16, nav);
        }

        {
            const float* Ah = AhB + cur * ASZ;
            const float* Al = AlB + cur * ASZ;
            const float* Bh = BhB + cur * BSZ;
            const float* Bl = BlB + cur * BSZ;
#pragma unroll
            for (int s = 0; s < 2; ++s) {
                int k0 = s * 8;
                uint32_t bh[4][2], bl[4][2];
#pragma unroll
                for (int nt = 0; nt < 4; ++nt) {
                    int j = col_base + nt * 8 + gid;
                    bh[nt][0] = __float_as_uint(Bh[(k0 + tig) * 136 + j]);
                    bh[nt][1] = __float_as_uint(Bh[(k0 + tig + 4) * 136 + j]);
                    bl[nt][0] = __float_as_uint(Bl[(k0 + tig) * 136 + j]);
                    bl[nt][1] = __float_as_uint(Bl[(k0 + tig + 4) * 136 + j]);
                }
#pragma unroll
                for (int mt = 0; mt < 4; ++mt) {
                    int m = row_base + mt * 16 + gid;
                    uint32_t ah[4], al[4];
                    ah[0] = __float_as_uint(Ah[m * 20 + k0 + tig]);
                    ah[1] = __float_as_uint(Ah[(m + 8) * 20 + k0 + tig]);
                    ah[2] = __float_as_uint(Ah[m * 20 + k0 + tig + 4]);
                    ah[3] = __float_as_uint(Ah[(m + 8) * 20 + k0 + tig + 4]);
                    al[0] = __float_as_uint(Al[m * 20 + k0 + tig]);
                    al[1] = __float_as_uint(Al[(m + 8) * 20 + k0 + tig]);
                    al[2] = __float_as_uint(Al[m * 20 + k0 + tig + 4]);
                    al[3] = __float_as_uint(Al[(m + 8) * 20 + k0 + tig + 4]);
#pragma unroll
                    for (int nt = 0; nt < 4; ++nt) {
                        MMA_TF32(acc[mt][nt], ah, bh[nt]);
                        MMA_TF32(acc[mt][nt], ah, bl[nt]);
                        MMA_TF32(acc[mt][nt], al, bh[nt]);
                    }
                }
            }
        }

        if (kc < 15) store_a(cur ^ 1, nav);
        asm volatile("cp.async.wait_group 0;");
        __syncthreads();
    }

    // ---- epilogue: bias + relu + row L2 norm ----
    float2 bias[4];
#pragma unroll
    for (int nt = 0; nt < 4; ++nt)
        bias[nt] = __ldg(reinterpret_cast<const float2*>(b) +
                         (col_base + nt * 8 + 2 * tig) / 2);

#pragma unroll
    for (int mt = 0; mt < 4; ++mt) {
#pragma unroll
        for (int r = 0; r < 2; ++r) {
            float part = 0.f;
#pragma unroll
            for (int nt = 0; nt < 4; ++nt) {
                float y0 = fmaxf(acc[mt][nt][2 * r]     + bias[nt].x, 0.f);
                float y1 = fmaxf(acc[mt][nt][2 * r + 1] + bias[nt].y, 0.f);
                acc[mt][nt][2 * r]     = y0;
                acc[mt][nt][2 * r + 1] = y1;
                part += y0 * y0 + y1 * y1;
            }
            part += __shfl_xor_sync(0xffffffffu, part, 1);
            part += __shfl_xor_sync(0xffffffffu, part, 2);
            if (tig == 0)
                atomicAdd(&norms[row_base + mt * 16 + gid + r * 8], part);
        }
    }
    __syncthreads();

#pragma unroll
    for (int mt = 0; mt < 4; ++mt) {
#pragma unroll
        for (int r = 0; r < 2; ++r) {
            int lrow = row_base + mt * 16 + gid + r * 8;
            int grow = n0 + lrow;
            if (grow < N_NODES) {
                float sc = 1.0f / fmaxf(sqrtf(norms[lrow]), 1e-12f);
#pragma unroll
                for (int nt = 0; nt < 4; ++nt) {
                    float2 o = make_float2(acc[mt][nt][2 * r] * sc,
                                           acc[mt][nt][2 * r + 1] * sc);
                    *reinterpret_cast<float2*>(out + (size_t)grow * F +
                                               col_base + nt * 8 + 2 * tig) = o;
                }
            }
        }
    }
}

// ---------------- layer 2a: project h2 -> pself(+bias) [N,16] and pn [N,16] ----------------
// pself -> g_h1, pn -> g_s. out = pself + mean_agg(pn) computed by agg16_kernel.
__global__ __launch_bounds__(256) void proj32_kernel(
    const float* __restrict__ hin,   // [N,128]
    const float* __restrict__ W,     // [16,256]
    const float* __restrict__ b)     // [16]
{
    int n = (blockIdx.x * blockDim.x + threadIdx.x) >> 5;
    if (n >= N_NODES) return;
    int l = threadIdx.x & 31;

    const float* hrow = hin + (size_t)n * F;
    float x[4];
#pragma unroll
    for (int i = 0; i < 4; ++i) x[i] = __ldg(hrow + l + 32 * i);

    float ps[16], pn[16];
#pragma unroll
    for (int j = 0; j < 16; ++j) {
        const float* wrow = W + j * 256;
        float as = 0.f, an = 0.f;
#pragma unroll
        for (int i = 0; i < 4; ++i) {
            as += x[i] * __ldg(wrow + l + 32 * i);
            an += x[i] * __ldg(wrow + 128 + l + 32 * i);
        }
#pragma unroll
        for (int off = 16; off; off >>= 1) {
            as += __shfl_xor_sync(0xffffffffu, as, off);
            an += __shfl_xor_sync(0xffffffffu, an, off);
        }
        ps[j] = as; pn[j] = an;
    }
    if (l < 16) {
        g_h1[(size_t)n * 16 + l] = ps[l] + __ldg(b + l);
        g_s [(size_t)n * 16 + l] = pn[l];
    }
}

// ---------------- layer 2b: 16-dim aggregation + final add ----------------
// warp per node: lanes split into two 16-lane halves, each handles alternate edges.
__global__ __launch_bounds__(256) void agg16_kernel(float* __restrict__ out) {
    int n = (blockIdx.x * blockDim.x + threadIdx.x) >> 5;
    if (n >= N_NODES) return;
    int lane = threadIdx.x & 31;
    int f = lane & 15, half = lane >> 4;
    int beg = g_off[n], end = g_off[n + 1];

    float acc = 0.f;
    for (int e = beg + half; e < end; e += 2) {
        int2 ew = __ldg(g_edge + e);
        float v = __ldg(g_s + (size_t)ew.x * 16 + f);
        acc += __int_as_float(ew.y) * v;
    }
    acc += __shfl_xor_sync(0xffffffffu, acc, 16);

    if (lane < 16) {
        float inv = (end > beg) ? 1.0f / (float)(end - beg) : 0.0f;
        out[(size_t)n * NCLS + f] = g_h1[(size_t)n * 16 + f] + acc * inv;
    }
}

// ---------------- launch ----------------
extern "C" void kernel_launch(void* const* d_in, const int* in_sizes, int n_in,
                              void* d_out, int out_size) {
    const float* h  = (const float*)d_in[0];
    const float* w  = (const float*)d_in[1];
    const int* src  = (const int*)d_in[2];
    const int* dst  = (const int*)d_in[3];
    const float* W0 = (const float*)d_in[4];
    const float* b0 = (const float*)d_in[5];
    const float* W1 = (const float*)d_in[6];
    const float* b1 = (const float*)d_in[7];
    const float* W2 = (const float*)d_in[8];
    const float* b2 = (const float*)d_in[9];
    float* out = (float*)d_out;

    void *ph1 = nullptr, *ph2 = nullptr;
    cudaGetSymbolAddress(&ph1, g_h1);
    cudaGetSymbolAddress(&ph2, g_h2);
    float* h1 = (float*)ph1;
    float* h2 = (float*)ph2;

    cudaFuncSetAttribute(sage_gemm_tf32,
                         cudaFuncAttributeMaxDynamicSharedMemorySize,
                         GEMM_SMEM_BYTES);

    const int NODE_BLOCKS = (N_NODES + 255) / 256;             // 157
    const int EDGE_BLOCKS = (N_EDGES + 255) / 256;             // 2500
    const int WARPN_BLOCKS = (N_NODES * 32 + 255) / 256;       // 5000
    const int GEMM_BLOCKS = (N_NODES + 127) / 128;             // 313
    const int WSP_BLOCKS  = (2 * 128 * 256 + 255) / 256;       // 256

    // weight pre-split (off the CSR critical path) + CSR build
    wsplit_all_kernel<<<WSP_BLOCKS, 256>>>(W0, W1);
    zero_cnt_kernel<<<NODE_BLOCKS, 256>>>();
    hist_kernel<<<EDGE_BLOCKS, 256>>>(dst);
    scan_kernel<<<1, 1024>>>();
    scatter_kernel<<<EDGE_BLOCKS, 256>>>(src, dst, w);

    // layer 0
    agg_csr_kernel<<<WARPN_BLOCKS, 256>>>((const float4*)h);
    sage_gemm_tf32<<<GEMM_BLOCKS, 256, GEMM_SMEM_BYTES>>>(h, b0, h1, 0);

    // layer 1
    agg_csr_kernel<<<WARPN_BLOCKS, 256>>>((const float4*)h1);
    sage_gemm_tf32<<<GEMM_BLOCKS, 256, GEMM_SMEM_BYTES>>>(h1, b1, h2, 1);

    // layer 2: project first (linearity), then 16-dim aggregate
    proj32_kernel<<<WARPN_BLOCKS, 256>>>(h2, W2, b2);
    agg16_kernel<<<WARPN_BLOCKS, 256>>>(out);
}

// round 5
// speedup vs baseline: 1.6552x; 1.2084x over previous
#include <cuda_runtime.h>
#include <math.h>
#include <stdint.h>

#define N_NODES 40000
#define N_EDGES 640000
#define F 128
#define NCLS 16

// ---------------- scratch (no allocations allowed) ----------------
__device__ float g_s[N_NODES * F];       // aggregation result / layer-2 pn
__device__ float g_h1[N_NODES * F];      // layer-0 output / layer-2 pself
__device__ float g_h2[N_NODES * F];      // layer-1 output
__device__ int   g_cnt[N_NODES];         // per-node edge count (histogram)
__device__ int   g_cur[N_NODES];         // scatter cursor
__device__ int   g_off[N_NODES];         // CSR range start (not node-ordered)
__device__ int   g_cursor;               // global range allocator
__device__ int2  g_edge[N_EDGES];        // CSR-sorted (src, w_bits)
__device__ float g_Whi[2 * 256 * 128];   // pre-split weight hi, k-major [layer][k][j]
__device__ float g_Wlo[2 * 256 * 128];   // pre-split weight lo, k-major [layer][k][j]

// ---------------- tf32 helpers ----------------
#define MMA_TF32(c, a, bb) \
    asm volatile("mma.sync.aligned.m16n8k8.row.col.f32.tf32.tf32.f32 " \
                 "{%0,%1,%2,%3}, {%4,%5,%6,%7}, {%8,%9}, {%0,%1,%2,%3};" \
                 : "+f"((c)[0]), "+f"((c)[1]), "+f"((c)[2]), "+f"((c)[3]) \
                 : "r"((a)[0]), "r"((a)[1]), "r"((a)[2]), "r"((a)[3]), \
                   "r"((bb)[0]), "r"((bb)[1]))

__device__ __forceinline__ void tf32_split(float x, float& hi, float& lo) {
    uint32_t hb;
    asm("cvt.rna.tf32.f32 %0, %1;" : "=r"(hb) : "f"(x));
    hi = __uint_as_float(hb);
    float l = x - hi;
    uint32_t lb;
    asm("cvt.rna.tf32.f32 %0, %1;" : "=r"(lb) : "f"(l));
    lo = __uint_as_float(lb);
}

__device__ __forceinline__ void cp_async16(void* smem_dst, const void* gsrc) {
    uint32_t d = (uint32_t)__cvta_generic_to_shared(smem_dst);
    asm volatile("cp.async.ca.shared.global [%0], [%1], 16;" :: "r"(d), "l"(gsrc));
}

// ---------------- weight pre-split: both layers in one launch ----------------
__global__ void wsplit_all_kernel(const float* __restrict__ W0,
                                  const float* __restrict__ W1) {
    int i = blockIdx.x * blockDim.x + threadIdx.x;
    if (i >= 2 * 128 * 256) return;
    int layer = i >> 15;
    int r = i & 32767;
    int j = r >> 8, k = r & 255;
    const float* W = layer ? W1 : W0;
    float hi, lo;
    tf32_split(W[r], hi, lo);
    g_Whi[layer * 32768 + k * 128 + j] = hi;
    g_Wlo[layer * 32768 + k * 128 + j] = lo;
}

// ---------------- CSR build (scan-free) ----------------
__global__ void zero_cnt_kernel() {
    int i = blockIdx.x * blockDim.x + threadIdx.x;
    if (i < N_NODES) g_cnt[i] = 0;
    if (i == 0) g_cursor = 0;
}

__global__ void hist_kernel(const int* __restrict__ dst) {
    int e = blockIdx.x * blockDim.x + threadIdx.x;
    if (e < N_EDGES) atomicAdd(&g_cnt[dst[e]], 1);
}

// Assign each node a contiguous range via warp-aggregated atomicAdd.
// Ranges are NOT in node order — irrelevant for correctness (per-node sums).
__global__ void offsets_kernel() {
    int i = blockIdx.x * blockDim.x + threadIdx.x;
    int lane = threadIdx.x & 31;
    int c = (i < N_NODES) ? g_cnt[i] : 0;
    int s = c;
#pragma unroll
    for (int off = 1; off < 32; off <<= 1) {
        int v = __shfl_up_sync(0xffffffffu, s, off);
        if (lane >= off) s += v;
    }
    int total = __shfl_sync(0xffffffffu, s, 31);
    int base = 0;
    if (lane == 0) base = atomicAdd(&g_cursor, total);
    base = __shfl_sync(0xffffffffu, base, 0);
    if (i < N_NODES) {
        g_off[i] = base + s - c;   // exclusive prefix within warp + warp base
        g_cur[i] = 0;
    }
}

__global__ void scatter_kernel(const int* __restrict__ src,
                               const int* __restrict__ dst,
                               const float* __restrict__ w) {
    int e = blockIdx.x * blockDim.x + threadIdx.x;
    if (e >= N_EDGES) return;
    int d = dst[e];
    int p = g_off[d] + atomicAdd(&g_cur[d], 1);
    g_edge[p] = make_int2(src[e], __float_as_int(w[e]));
}

// ---------------- aggregation (d=128): warp per node, register accumulate ----------------
__global__ __launch_bounds__(256) void agg_csr_kernel(const float4* __restrict__ hin) {
    int n = (blockIdx.x * blockDim.x + threadIdx.x) >> 5;
    if (n >= N_NODES) return;
    int lane = threadIdx.x & 31;
    int beg = g_off[n];
    int end = beg + g_cnt[n];

    float4 a0 = make_float4(0.f, 0.f, 0.f, 0.f);
    float4 a1 = make_float4(0.f, 0.f, 0.f, 0.f);
    int e = beg;
    for (; e + 2 <= end; e += 2) {
        int2 e0 = __ldg(g_edge + e);
        int2 e1 = __ldg(g_edge + e + 1);
        float w0 = __int_as_float(e0.y), w1 = __int_as_float(e1.y);
        float4 v0 = __ldg(hin + (size_t)e0.x * 32 + lane);
        float4 v1 = __ldg(hin + (size_t)e1.x * 32 + lane);
        a0.x += w0 * v0.x; a0.y += w0 * v0.y; a0.z += w0 * v0.z; a0.w += w0 * v0.w;
        a1.x += w1 * v1.x; a1.y += w1 * v1.y; a1.z += w1 * v1.z; a1.w += w1 * v1.w;
    }
    if (e < end) {
        int2 e0 = __ldg(g_edge + e);
        float w0 = __int_as_float(e0.y);
        float4 v0 = __ldg(hin + (size_t)e0.x * 32 + lane);
        a0.x += w0 * v0.x; a0.y += w0 * v0.y; a0.z += w0 * v0.z; a0.w += w0 * v0.w;
    }
    float inv = (end > beg) ? 1.0f / (float)(end - beg) : 0.0f;
    float4 r = make_float4((a0.x + a1.x) * inv, (a0.y + a1.y) * inv,
                           (a0.z + a1.z) * inv, (a0.w + a1.w) * inv);
    reinterpret_cast<float4*>(g_s)[(size_t)n * 32 + lane] = r;
}

// ---------------- 3xTF32 GEMM, double-buffered, cp.async B ----------------
#define ASZ (128 * 20)
#define BSZ (16 * 136)
#define GEMM_SMEM_BYTES ((4 * ASZ + 4 * BSZ + 128) * 4)

__global__ __launch_bounds__(256, 2) void sage_gemm_tf32(
    const float* __restrict__ hin,   // [N,128] layer input
    const float* __restrict__ b,     // [128]
    float* __restrict__ out,         // [N,128]
    int layer)
{
    extern __shared__ float smem[];
    float* AhB = smem;                    // [2][ASZ]
    float* AlB = AhB + 2 * ASZ;
    float* BhB = AlB + 2 * ASZ;           // [2][BSZ]
    float* BlB = BhB + 2 * BSZ;
    float* norms = BlB + 2 * BSZ;         // [128]

    const float* Whi = g_Whi + layer * 32768;
    const float* Wlo = g_Wlo + layer * 32768;

    int t = threadIdx.x;
    int n0 = blockIdx.x * 128;
    int warp = t >> 5, lane = t & 31;
    int wr = warp >> 2, wc = warp & 3;
    int row_base = wr * 64;
    int col_base = wc * 32;
    int gid = lane >> 2, tig = lane & 3;

    if (t < 128) norms[t] = 0.f;

    float acc[4][4][4];
#pragma unroll
    for (int mt = 0; mt < 4; ++mt)
#pragma unroll
        for (int nt = 0; nt < 4; ++nt)
#pragma unroll
            for (int c = 0; c < 4; ++c) acc[mt][nt][c] = 0.f;

    const float4* hin4 = reinterpret_cast<const float4*>(hin);
    const float4* s4   = reinterpret_cast<const float4*>(g_s);

    int m_[2], f_[2];
#pragma unroll
    for (int i = 0; i < 2; ++i) { int q = t + i * 256; m_[i] = q >> 2; f_[i] = q & 3; }
    int bk_[2], bj_[2];
#pragma unroll
    for (int i = 0; i < 2; ++i) { int q = t + i * 256; bk_[i] = q >> 5; bj_[i] = q & 31; }

    auto load_a = [&](int kg, float4 v[2]) {
#pragma unroll
        for (int i = 0; i < 2; ++i) {
            int grow = n0 + m_[i];
            float4 x = make_float4(0.f, 0.f, 0.f, 0.f);
            if (grow < N_NODES) {
                x = (kg < 128)
                    ? __ldg(hin4 + (size_t)grow * 32 + (kg >> 2) + f_[i])
                    : __ldg(s4   + (size_t)grow * 32 + ((kg - 128) >> 2) + f_[i]);
            }
            v[i] = x;
        }
    };
    auto store_a = [&](int buf, const float4 v[2]) {
        float* Ah = AhB + buf * ASZ;
        float* Al = AlB + buf * ASZ;
#pragma unroll
        for (int i = 0; i < 2; ++i) {
            float xs[4] = {v[i].x, v[i].y, v[i].z, v[i].w};
            float h4[4], l4[4];
#pragma unroll
            for (int c = 0; c < 4; ++c) tf32_split(xs[c], h4[c], l4[c]);
            int base = m_[i] * 20 + f_[i] * 4;
            *reinterpret_cast<float4*>(Ah + base) = make_float4(h4[0], h4[1], h4[2], h4[3]);
            *reinterpret_cast<float4*>(Al + base) = make_float4(l4[0], l4[1], l4[2], l4[3]);
        }
    };
    auto issue_b = [&](int kg, int buf) {
        float* Bh = BhB + buf * BSZ;
        float* Bl = BlB + buf * BSZ;
#pragma unroll
        for (int i = 0; i < 2; ++i) {
            int off = bk_[i] * 136 + bj_[i] * 4;
            cp_async16(Bh + off, Whi + (size_t)(kg + bk_[i]) * 128 + bj_[i] * 4);
            cp_async16(Bl + off, Wlo + (size_t)(kg + bk_[i]) * 128 + bj_[i] * 4);
        }
        asm volatile("cp.async.commit_group;");
    };

    float4 av[2];
    issue_b(0, 0);
    load_a(0, av);
    store_a(0, av);
    asm volatile("cp.async.wait_group 0;");
    __syncthreads();

    for (int kc = 0; kc < 16; ++kc) {
        int cur = kc & 1;
        float4 nav[2];
        if (kc < 15) {
            issue_b((kc + 1) * 16, cur ^ 1);
            load_a((kc + 1) * 16, nav);
        }

        {
            const float* Ah = AhB + cur * ASZ;
            const float* Al = AlB + cur * ASZ;
            const float* Bh = BhB + cur * BSZ;
            const float* Bl = BlB + cur * BSZ;
#pragma unroll
            for (int s = 0; s < 2; ++s) {
                int k0 = s * 8;
                uint32_t bh[4][2], bl[4][2];
#pragma unroll
                for (int nt = 0; nt < 4; ++nt) {
                    int j = col_base + nt * 8 + gid;
                    bh[nt][0] = __float_as_uint(Bh[(k0 + tig) * 136 + j]);
                    bh[nt][1] = __float_as_uint(Bh[(k0 + tig + 4) * 136 + j]);
                    bl[nt][0] = __float_as_uint(Bl[(k0 + tig) * 136 + j]);
                    bl[nt][1] = __float_as_uint(Bl[(k0 + tig + 4) * 136 + j]);
                }
#pragma unroll
                for (int mt = 0; mt < 4; ++mt) {
                    int m = row_base + mt * 16 + gid;
                    uint32_t ah[4], al[4];
                    ah[0] = __float_as_uint(Ah[m * 20 + k0 + tig]);
                    ah[1] = __float_as_uint(Ah[(m + 8) * 20 + k0 + tig]);
                    ah[2] = __float_as_uint(Ah[m * 20 + k0 + tig + 4]);
                    ah[3] = __float_as_uint(Ah[(m + 8) * 20 + k0 + tig + 4]);
                    al[0] = __float_as_uint(Al[m * 20 + k0 + tig]);
                    al[1] = __float_as_uint(Al[(m + 8) * 20 + k0 + tig]);
                    al[2] = __float_as_uint(Al[m * 20 + k0 + tig + 4]);
                    al[3] = __float_as_uint(Al[(m + 8) * 20 + k0 + tig + 4]);
#pragma unroll
                    for (int nt = 0; nt < 4; ++nt) {
                        MMA_TF32(acc[mt][nt], ah, bh[nt]);
                        MMA_TF32(acc[mt][nt], ah, bl[nt]);
                        MMA_TF32(acc[mt][nt], al, bh[nt]);
                    }
                }
            }
        }

        if (kc < 15) store_a(cur ^ 1, nav);
        asm volatile("cp.async.wait_group 0;");
        __syncthreads();
    }

    // ---- epilogue: bias + relu + row L2 norm ----
    float2 bias[4];
#pragma unroll
    for (int nt = 0; nt < 4; ++nt)
        bias[nt] = __ldg(reinterpret_cast<const float2*>(b) +
                         (col_base + nt * 8 + 2 * tig) / 2);

#pragma unroll
    for (int mt = 0; mt < 4; ++mt) {
#pragma unroll
        for (int r = 0; r < 2; ++r) {
            float part = 0.f;
#pragma unroll
            for (int nt = 0; nt < 4; ++nt) {
                float y0 = fmaxf(acc[mt][nt][2 * r]     + bias[nt].x, 0.f);
                float y1 = fmaxf(acc[mt][nt][2 * r + 1] + bias[nt].y, 0.f);
                acc[mt][nt][2 * r]     = y0;
                acc[mt][nt][2 * r + 1] = y1;
                part += y0 * y0 + y1 * y1;
            }
            part += __shfl_xor_sync(0xffffffffu, part, 1);
            part += __shfl_xor_sync(0xffffffffu, part, 2);
            if (tig == 0)
                atomicAdd(&norms[row_base + mt * 16 + gid + r * 8], part);
        }
    }
    __syncthreads();

#pragma unroll
    for (int mt = 0; mt < 4; ++mt) {
#pragma unroll
        for (int r = 0; r < 2; ++r) {
            int lrow = row_base + mt * 16 + gid + r * 8;
            int grow = n0 + lrow;
            if (grow < N_NODES) {
                float sc = 1.0f / fmaxf(sqrtf(norms[lrow]), 1e-12f);
#pragma unroll
                for (int nt = 0; nt < 4; ++nt) {
                    float2 o = make_float2(acc[mt][nt][2 * r] * sc,
                                           acc[mt][nt][2 * r + 1] * sc);
                    *reinterpret_cast<float2*>(out + (size_t)grow * F +
                                               col_base + nt * 8 + 2 * tig) = o;
                }
            }
        }
    }
}

// ---------------- layer 2a: project h2 -> pself(+bias) [N,16] and pn [N,16] ----------------
__global__ __launch_bounds__(256) void proj32_kernel(
    const float* __restrict__ hin,   // [N,128]
    const float* __restrict__ W,     // [16,256]
    const float* __restrict__ b)     // [16]
{
    int n = (blockIdx.x * blockDim.x + threadIdx.x) >> 5;
    if (n >= N_NODES) return;
    int l = threadIdx.x & 31;

    const float* hrow = hin + (size_t)n * F;
    float x[4];
#pragma unroll
    for (int i = 0; i < 4; ++i) x[i] = __ldg(hrow + l + 32 * i);

    float ps[16], pn[16];
#pragma unroll
    for (int j = 0; j < 16; ++j) {
        const float* wrow = W + j * 256;
        float as = 0.f, an = 0.f;
#pragma unroll
        for (int i = 0; i < 4; ++i) {
            as += x[i] * __ldg(wrow + l + 32 * i);
            an += x[i] * __ldg(wrow + 128 + l + 32 * i);
        }
#pragma unroll
        for (int off = 16; off; off >>= 1) {
            as += __shfl_xor_sync(0xffffffffu, as, off);
            an += __shfl_xor_sync(0xffffffffu, an, off);
        }
        ps[j] = as; pn[j] = an;
    }
    if (l < 16) {
        g_h1[(size_t)n * 16 + l] = ps[l] + __ldg(b + l);
        g_s [(size_t)n * 16 + l] = pn[l];
    }
}

// ---------------- layer 2b: 16-dim aggregation + final add ----------------
__global__ __launch_bounds__(256) void agg16_kernel(float* __restrict__ out) {
    int n = (blockIdx.x * blockDim.x + threadIdx.x) >> 5;
    if (n >= N_NODES) return;
    int lane = threadIdx.x & 31;
    int f = lane & 15, half = lane >> 4;
    int beg = g_off[n];
    int end = beg + g_cnt[n];

    float acc = 0.f;
    for (int e = beg + half; e < end; e += 2) {
        int2 ew = __ldg(g_edge + e);
        float v = __ldg(g_s + (size_t)ew.x * 16 + f);
        acc += __int_as_float(ew.y) * v;
    }
    acc += __shfl_xor_sync(0xffffffffu, acc, 16);

    if (lane < 16) {
        float inv = (end > beg) ? 1.0f / (float)(end - beg) : 0.0f;
        out[(size_t)n * NCLS + f] = g_h1[(size_t)n * 16 + f] + acc * inv;
    }
}

// ---------------- launch ----------------
extern "C" void kernel_launch(void* const* d_in, const int* in_sizes, int n_in,
                              void* d_out, int out_size) {
    const float* h  = (const float*)d_in[0];
    const float* w  = (const float*)d_in[1];
    const int* src  = (const int*)d_in[2];
    const int* dst  = (const int*)d_in[3];
    const float* W0 = (const float*)d_in[4];
    const float* b0 = (const float*)d_in[5];
    const float* W1 = (const float*)d_in[6];
    const float* b1 = (const float*)d_in[7];
    const float* W2 = (const float*)d_in[8];
    const float* b2 = (const float*)d_in[9];
    float* out = (float*)d_out;

    void *ph1 = nullptr, *ph2 = nullptr;
    cudaGetSymbolAddress(&ph1, g_h1);
    cudaGetSymbolAddress(&ph2, g_h2);
    float* h1 = (float*)ph1;
    float* h2 = (float*)ph2;

    cudaFuncSetAttribute(sage_gemm_tf32,
                         cudaFuncAttributeMaxDynamicSharedMemorySize,
                         GEMM_SMEM_BYTES);

    const int NODE_BLOCKS = (N_NODES + 255) / 256;             // 157
    const int EDGE_BLOCKS = (N_EDGES + 255) / 256;             // 2500
    const int WARPN_BLOCKS = (N_NODES * 32 + 255) / 256;       // 5000
    const int GEMM_BLOCKS = (N_NODES + 127) / 128;             // 313

    const int WSP_BLOCKS  = (2 * 128 * 256 + 255) / 256;       // 256

    // weight pre-split + scan-free CSR build
    wsplit_all_kernel<<<WSP_BLOCKS, 256>>>(W0, W1);
    zero_cnt_kernel<<<NODE_BLOCKS, 256>>>();
    hist_kernel<<<EDGE_BLOCKS, 256>>>(dst);
    offsets_kernel<<<NODE_BLOCKS, 256>>>();
    scatter_kernel<<<EDGE_BLOCKS, 256>>>(src, dst, w);

    // layer 0
    agg_csr_kernel<<<WARPN_BLOCKS, 256>>>((const float4*)h);
    sage_gemm_tf32<<<GEMM_BLOCKS, 256, GEMM_SMEM_BYTES>>>(h, b0, h1, 0);

    // layer 1
    agg_csr_kernel<<<WARPN_BLOCKS, 256>>>((const float4*)h1);
    sage_gemm_tf32<<<GEMM_BLOCKS, 256, GEMM_SMEM_BYTES>>>(h1, b1, h2, 1);

    // layer 2: project first (linearity), then 16-dim aggregate
    proj32_kernel<<<WARPN_BLOCKS, 256>>>(h2, W2, b2);
    agg16_kernel<<<WARPN_BLOCKS, 256>>>(out);
}